// round 9
// baseline (speedup 1.0000x reference)
#include <cuda_runtime.h>

#define NB 64
#define NS 256
#define NI 256
#define NHH 512
#define N2H 1024
#define NM (NB*NS)

// Scratch for the pre-activation GEMM output i = x @ W^T   [16384 x 1024], 64MB
static __device__ float g_C[(size_t)NM * N2H];

typedef unsigned long long u64;
__device__ __forceinline__ u64 pk2(float lo, float hi){ u64 r; asm("mov.b64 %0,{%1,%2};" : "=l"(r) : "f"(lo), "f"(hi)); return r; }
__device__ __forceinline__ void up2(u64 a, float& lo, float& hi){ asm("mov.b64 {%0,%1},%2;" : "=f"(lo), "=f"(hi) : "l"(a)); }
__device__ __forceinline__ u64 fma2(u64 a, u64 b, u64 c){ u64 d; asm("fma.rn.f32x2 %0,%1,%2,%3;" : "=l"(d) : "l"(a), "l"(b), "l"(c)); return d; }
__device__ __forceinline__ u64 mul2(u64 a, u64 b){ u64 d; asm("mul.rn.f32x2 %0,%1,%2;" : "=l"(d) : "l"(a), "l"(b)); return d; }
__device__ __forceinline__ u64 add2(u64 a, u64 b){ u64 d; asm("add.rn.f32x2 %0,%1,%2;" : "=l"(d) : "l"(a), "l"(b)); return d; }

// Exact-ish tanh for the trace kernel (rel err ~1e-6).
__device__ __forceinline__ float fast_tanh(float x){
    float z = __expf(2.0f * x);
    return 1.0f - __fdividef(2.0f, z + 1.0f);
}
// Single-instruction MUFU.TANH (sm_75+), rel err ~1.6e-5.
__device__ __forceinline__ float tanh_approx(float x){
    float r; asm("tanh.approx.f32 %0, %1;" : "=f"(r) : "f"(x)); return r;
}

union F4U { float4 f; u64 u[2]; };

// ---------------------------------------------------------------------------
// Kernel 1: SGEMM  C[m][n] = sum_k x[m][k] * W[n][k]
// EXACT R2 version (201us measured = the fp32 FFMA roofline on this part).
// ---------------------------------------------------------------------------
#define BM 128
#define BN 128
#define BK 32

__global__ __launch_bounds__(256) void sgemm_kernel(const float* __restrict__ A,
                                                    const float* __restrict__ W)
{
    __shared__ float As[BK][BM+4];
    __shared__ float Bs[BK][BN+4];
    const int tid = threadIdx.x;
    const int m0 = blockIdx.y * BM;
    const int n0 = blockIdx.x * BN;
    const int tr = tid >> 4;        // 0..15
    const int tc = tid & 15;        // 0..15

    float acc[8][8];
    #pragma unroll
    for (int i=0;i<8;i++)
        #pragma unroll
        for (int j=0;j<8;j++) acc[i][j]=0.f;

    const int lr = tid >> 3;          // 0..31
    const int lc = (tid & 7) << 2;    // 0,4,...,28

    for (int k0=0; k0<NI; k0+=BK){
        #pragma unroll
        for (int h=0; h<4; h++){
            int r = lr + h*32;
            float4 av = *(const float4*)(A + (size_t)(m0+r)*NI + k0 + lc);
            As[lc+0][r]=av.x; As[lc+1][r]=av.y; As[lc+2][r]=av.z; As[lc+3][r]=av.w;
            float4 bv = *(const float4*)(W + (size_t)(n0+r)*NI + k0 + lc);
            Bs[lc+0][r]=bv.x; Bs[lc+1][r]=bv.y; Bs[lc+2][r]=bv.z; Bs[lc+3][r]=bv.w;
        }
        __syncthreads();
        #pragma unroll
        for (int kk=0;kk<BK;kk++){
            float a[8], bb[8];
            *(float4*)(a)    = *(const float4*)(&As[kk][tr*8]);
            *(float4*)(a+4)  = *(const float4*)(&As[kk][tr*8+4]);
            *(float4*)(bb)   = *(const float4*)(&Bs[kk][tc*8]);
            *(float4*)(bb+4) = *(const float4*)(&Bs[kk][tc*8+4]);
            #pragma unroll
            for (int i=0;i<8;i++)
                #pragma unroll
                for (int j=0;j<8;j++)
                    acc[i][j] = fmaf(a[i], bb[j], acc[i][j]);
        }
        __syncthreads();
    }
    #pragma unroll
    for (int i=0;i<8;i++){
        float* cptr = g_C + (size_t)(m0 + tr*8 + i)*N2H + n0 + tc*8;
        *(float4*)(cptr)   = make_float4(acc[i][0],acc[i][1],acc[i][2],acc[i][3]);
        *(float4*)(cptr+4) = make_float4(acc[i][4],acc[i][5],acc[i][6],acc[i][7]);
    }
}

// ---------------------------------------------------------------------------
// Kernel 2: k-trace precompute.
// ---------------------------------------------------------------------------
__global__ __launch_bounds__(256) void trace_kernel(float* __restrict__ keys_out)
{
    int gid = blockIdx.x*blockDim.x + threadIdx.x;   // 0..32767
    int b = gid >> 9;
    int h = gid & 511;
    const float* c = g_C + (size_t)b*NS*N2H + h;      // ik column
    float* ko = keys_out + (size_t)b*NS*NHH + h;
    const float ALPHA = 0.9048374180359595f;
    float ks = 0.f;
    #pragma unroll 8
    for (int t=0;t<NS;t++){
        ks = fmaf(ks, ALPHA, __ldg(c + (size_t)t*N2H));
        ko[(size_t)t*NHH] = fast_tanh(ks);
    }
}

// ---------------------------------------------------------------------------
// Kernel 3: main recurrence, OCCUPANCY-OPTIMIZED: 2 rows/warp, 256-thread
// blocks, launch_bounds(256,3) -> 6 warps/SMSP (2x the latency hiding of the
// 4-row version; recur is at 31% of the fp32 roofline due to stalls, not work).
// m'' = mem/P in registers (32 regs), k_t staged via double-buffered smem,
// scalar chain in UNPACKED floats with immediate-constant FFMA (no const regs).
// Grid: (32 row-groups, 64 batches) x 256 threads (8 warps x 2 rows).
// ---------------------------------------------------------------------------
__global__ __launch_bounds__(256, 3) void recur_kernel(const float* __restrict__ keys,
                                                       float* __restrict__ mem_out,
                                                       float* __restrict__ vals_out)
{
    __shared__ float sk[2][NHH];

    const int b    = blockIdx.y;
    const int rg   = blockIdx.x;       // 0..31
    const int tid  = threadIdx.x;
    const int warp = tid >> 5;         // 0..7
    const int lane = tid & 31;
    const int row0 = rg*16 + warp*2;

    u64 m0[8], m1[8], kt[8];
    #pragma unroll
    for (int p=0;p<8;p++){ m0[p]=0ULL; m1[p]=0ULL; kt[p]=0ULL; }

    // scalar state, plain floats (constants become FFMA immediates)
    float vs0=0.f, vs1=0.f, vt0=0.f, vt1=0.f;
    float P0=1.f, P1=1.f;
    float Q0=0.000487705754993f, Q1=0.000487705754993f;   // LR*(1-DEC)

    const float* kg  = keys + (size_t)b*NS*NHH;
    const float* ivb = g_C + (size_t)b*NS*N2H + NHH + row0;
    float*       vb  = vals_out + (size_t)b*NS*NHH + row0;

    // preload k_0 into sk[0] (256 threads x float2 = 512 floats)
    *(float2*)(&sk[0][tid*2]) = *(const float2*)(kg + tid*2);
    float2 knext = *(const float2*)(kg + NHH + tid*2);
    float2 ivf = __ldg((const float2*)ivb);
    __syncthreads();

    for (int t=0;t<NS;t++){
        const int cur = t & 1;
        // early loads for next step
        float2 ivn = __ldg((const float2*)(ivb + (size_t)((t+1<NS)?(t+1):t)*N2H));

        // read k_t from smem; dots (two trees per row) + kt' update fused per chunk
        u64 a0s0=0ULL, a0s1=0ULL, a1s0=0ULL, a1s1=0ULL;
        #pragma unroll
        for (int c=0;c<4;c++){
            F4U kv; kv.f = *(const float4*)(&sk[cur][c*128 + lane*4]);
            const int p = 2*c;
            a0s0 = fma2(m0[p],   kv.u[0], a0s0);
            a0s1 = fma2(m0[p+1], kv.u[1], a0s1);
            a1s0 = fma2(m1[p],   kv.u[0], a1s0);
            a1s1 = fma2(m1[p+1], kv.u[1], a1s1);
            kt[p]   = fma2(kt[p],   pk2(0.9512294245f,0.9512294245f), kv.u[0]);
            kt[p+1] = fma2(kt[p+1], pk2(0.9512294245f,0.9512294245f), kv.u[1]);
        }
        u64 a0 = add2(a0s0, a0s1);
        u64 a1 = add2(a1s0, a1s1);

        // horizontal + butterfly allreduce (one packed chain for both rows)
        float x,y;
        up2(a0,x,y); float h0 = x+y;
        up2(a1,x,y); float h1 = x+y;
        u64 r01 = pk2(h0,h1);
        #pragma unroll
        for (int o=16;o;o>>=1)
            r01 = add2(r01, __shfl_xor_sync(0xffffffffu, r01, o));
        float dot0, dot1; up2(r01, dot0, dot1);

        // scalar chains (immediate-form FFMA, warp-uniform)
        float d0 = P0*dot0, d1 = P1*dot1;
        vs0 = fmaf(vs0, 0.9048374180f, fmaf(0.2f, d0, ivf.x));
        vs1 = fmaf(vs1, 0.9048374180f, fmaf(0.2f, d1, ivf.y));
        float v0 = tanh_approx(vs0), v1 = tanh_approx(vs1);
        vt0 = fmaf(0.0487705755f, v0, 0.9512294245f*vt0);
        vt1 = fmaf(0.0487705755f, v1, 0.9512294245f*vt1);
        float e0 = 0.01f*vt0*vt0, e1 = 0.01f*vt1*vt1;
        P0 *= (1.0f - e0);
        P1 *= (1.0f - e1);
        // 1/(1-e) ~= 1+e+e^2+e^3  (err ~ e^4 <= 1e-8)
        Q0 *= fmaf(e0, fmaf(e0, 1.0f + e0, 1.0f), 1.0f);
        Q1 *= fmaf(e1, fmaf(e1, 1.0f + e1, 1.0f), 1.0f);
        float w0 = Q0*vt0, w1 = Q1*vt1;

        if (lane == 0)
            *(float2*)(vb + (size_t)t*NHH) = make_float2(v0, v1);

        // scaled mem update: m''_r += kt' * w_r
        u64 wp0 = pk2(w0,w0), wp1 = pk2(w1,w1);
        #pragma unroll
        for (int p=0;p<8;p++){
            m0[p] = fma2(kt[p], wp0, m0[p]);
            m1[p] = fma2(kt[p], wp1, m1[p]);
        }

        // stage k_{t+1}; prefetch k_{t+2}; one sync per step
        *(float2*)(&sk[cur^1][tid*2]) = knext;
        if (t+2 < NS) knext = *(const float2*)(kg + (size_t)(t+2)*NHH + tid*2);
        ivf = ivn;
        __syncthreads();
    }

    // write final mem rows: mem = P_r * m''_r
    {
        u64 Pp0 = pk2(P0,P0), Pp1 = pk2(P1,P1);
        float* mo = mem_out + ((size_t)b*NHH + row0)*NHH + lane*4;
        #pragma unroll
        for (int c=0;c<4;c++){
            F4U u0; u0.u[0]=mul2(m0[2*c],Pp0); u0.u[1]=mul2(m0[2*c+1],Pp0);
            *(float4*)(mo + c*128) = u0.f;
            F4U u1; u1.u[0]=mul2(m1[2*c],Pp1); u1.u[1]=mul2(m1[2*c+1],Pp1);
            *(float4*)(mo + NHH + c*128) = u1.f;
        }
    }
}

// ---------------------------------------------------------------------------
extern "C" void kernel_launch(void* const* d_in, const int* in_sizes, int n_in,
                              void* d_out, int out_size)
{
    const float* x = (const float*)d_in[0];   // [64,256,256]
    const float* W = (const float*)d_in[1];   // [1024,256]
    float* out = (float*)d_out;
    float* mem_out  = out;                                    // [64,512,512]
    float* keys_out = out + (size_t)NB*NHH*NHH;               // [64,256,512]
    float* vals_out = keys_out + (size_t)NB*NS*NHH;           // [64,256,512]

    dim3 g1(N2H/BN, NM/BM);                 // (8, 128)
    sgemm_kernel<<<g1, 256>>>(x, W);
    trace_kernel<<<(NB*NHH)/256, 256>>>(keys_out);
    recur_kernel<<<dim3(32, NB), 256>>>(keys_out, mem_out, vals_out);
}

// round 11
// speedup vs baseline: 1.4486x; 1.4486x over previous
#include <cuda_runtime.h>

#define NB 64
#define NS 256
#define NI 256
#define NHH 512
#define N2H 1024
#define NM (NB*NS)
#define CS 64          // scan chunk size
#define NC (NS/CS)     // 4 chunks

// Scratch (static device arrays)
static __device__ float g_C  [(size_t)NM * N2H];        // x@W^T           64MB
static __device__ float g_KTP[(size_t)NB * NS * NHH];   // kt' traces      33MB
static __device__ float g_WQ [(size_t)NB * NS * NHH];   // wq[b][s][r]     33MB
static __device__ float g_G  [(size_t)NB * NS * NS];    // Gram[b][s][t]   16MB
static __device__ float g_BASE[(size_t)NB * NHH * CS];  // per-chunk base   8MB
static __device__ float g_SVS[NB*NHH], g_SVT[NB*NHH], g_SP[NB*NHH], g_SQ[NB*NHH];

__device__ __forceinline__ float fast_tanh(float x){
    float z = __expf(2.0f * x);
    return 1.0f - __fdividef(2.0f, z + 1.0f);
}
__device__ __forceinline__ float tanh_approx(float x){
    float r; asm("tanh.approx.f32 %0, %1;" : "=f"(r) : "f"(x)); return r;
}

#define ALPHA 0.9048374180359595f
#define DECAY 0.9512294245007140f
#define OMD   0.0487705754992860f
#define LRC   0.01f

// ---------------------------------------------------------------------------
// Kernel 1: SGEMM  C[m][n] = sum_k x[m][k]*W[n][k]  (measured 201us)
// ---------------------------------------------------------------------------
__global__ __launch_bounds__(256) void sgemm_kernel(const float* __restrict__ A,
                                                    const float* __restrict__ W)
{
    __shared__ float As[32][128+4];
    __shared__ float Bs[32][128+4];
    const int tid = threadIdx.x;
    const int m0 = blockIdx.y * 128;
    const int n0 = blockIdx.x * 128;
    const int tr = tid >> 4, tc = tid & 15;
    float acc[8][8];
    #pragma unroll
    for (int i=0;i<8;i++)
        #pragma unroll
        for (int j=0;j<8;j++) acc[i][j]=0.f;
    const int lr = tid >> 3, lc = (tid & 7) << 2;
    for (int k0=0; k0<NI; k0+=32){
        #pragma unroll
        for (int h=0; h<4; h++){
            int r = lr + h*32;
            float4 av = *(const float4*)(A + (size_t)(m0+r)*NI + k0 + lc);
            As[lc+0][r]=av.x; As[lc+1][r]=av.y; As[lc+2][r]=av.z; As[lc+3][r]=av.w;
            float4 bv = *(const float4*)(W + (size_t)(n0+r)*NI + k0 + lc);
            Bs[lc+0][r]=bv.x; Bs[lc+1][r]=bv.y; Bs[lc+2][r]=bv.z; Bs[lc+3][r]=bv.w;
        }
        __syncthreads();
        #pragma unroll
        for (int kk=0;kk<32;kk++){
            float a[8], bb[8];
            *(float4*)(a)    = *(const float4*)(&As[kk][tr*8]);
            *(float4*)(a+4)  = *(const float4*)(&As[kk][tr*8+4]);
            *(float4*)(bb)   = *(const float4*)(&Bs[kk][tc*8]);
            *(float4*)(bb+4) = *(const float4*)(&Bs[kk][tc*8+4]);
            #pragma unroll
            for (int i=0;i<8;i++)
                #pragma unroll
                for (int j=0;j<8;j++)
                    acc[i][j] = fmaf(a[i], bb[j], acc[i][j]);
        }
        __syncthreads();
    }
    #pragma unroll
    for (int i=0;i<8;i++){
        float* cptr = g_C + (size_t)(m0 + tr*8 + i)*N2H + n0 + tc*8;
        *(float4*)(cptr)   = make_float4(acc[i][0],acc[i][1],acc[i][2],acc[i][3]);
        *(float4*)(cptr+4) = make_float4(acc[i][4],acc[i][5],acc[i][6],acc[i][7]);
    }
}

// ---------------------------------------------------------------------------
// Kernel 2: per-(b,h) sequential traces: keys = tanh(ks), kt' = d*kt' + key
// ---------------------------------------------------------------------------
__global__ __launch_bounds__(256) void tracek_kernel(float* __restrict__ keys_out)
{
    int gid = blockIdx.x*blockDim.x + threadIdx.x;
    int b = gid >> 9, h = gid & 511;
    const float* c = g_C + (size_t)b*NS*N2H + h;
    float* ko = keys_out + (size_t)b*NS*NHH + h;
    float* kp = g_KTP    + (size_t)b*NS*NHH + h;
    float ks = 0.f, kt = 0.f;
    #pragma unroll 8
    for (int t=0;t<NS;t++){
        ks = fmaf(ks, ALPHA, __ldg(c + (size_t)t*N2H));
        float k = fast_tanh(ks);
        ko[(size_t)t*NHH] = k;
        kt = fmaf(kt, DECAY, k);
        kp[(size_t)t*NHH] = kt;
    }
}

// ---------------------------------------------------------------------------
// Kernel 3: batched Gram  G[b][s][t] = sum_h KTP[b][s][h]*keys[b][t][h]
// M=N=256, K=512, 128x128 tiles, grid (2,2,64)
// ---------------------------------------------------------------------------
__global__ __launch_bounds__(256) void gram_kernel(const float* __restrict__ keys)
{
    __shared__ float As[32][128+4];
    __shared__ float Bs[32][128+4];
    const int tid = threadIdx.x;
    const int b  = blockIdx.z;
    const int m0 = blockIdx.y * 128;
    const int n0 = blockIdx.x * 128;
    const float* A = g_KTP + (size_t)b*NS*NHH;
    const float* B = keys  + (size_t)b*NS*NHH;
    const int tr = tid >> 4, tc = tid & 15;
    float acc[8][8];
    #pragma unroll
    for (int i=0;i<8;i++)
        #pragma unroll
        for (int j=0;j<8;j++) acc[i][j]=0.f;
    const int lr = tid >> 3, lc = (tid & 7) << 2;
    for (int k0=0; k0<NHH; k0+=32){
        #pragma unroll
        for (int h=0; h<4; h++){
            int r = lr + h*32;
            float4 av = *(const float4*)(A + (size_t)(m0+r)*NHH + k0 + lc);
            As[lc+0][r]=av.x; As[lc+1][r]=av.y; As[lc+2][r]=av.z; As[lc+3][r]=av.w;
            float4 bv = *(const float4*)(B + (size_t)(n0+r)*NHH + k0 + lc);
            Bs[lc+0][r]=bv.x; Bs[lc+1][r]=bv.y; Bs[lc+2][r]=bv.z; Bs[lc+3][r]=bv.w;
        }
        __syncthreads();
        #pragma unroll
        for (int kk=0;kk<32;kk++){
            float a[8], bb[8];
            *(float4*)(a)    = *(const float4*)(&As[kk][tr*8]);
            *(float4*)(a+4)  = *(const float4*)(&As[kk][tr*8+4]);
            *(float4*)(bb)   = *(const float4*)(&Bs[kk][tc*8]);
            *(float4*)(bb+4) = *(const float4*)(&Bs[kk][tc*8+4]);
            #pragma unroll
            for (int i=0;i<8;i++)
                #pragma unroll
                for (int j=0;j<8;j++)
                    acc[i][j] = fmaf(a[i], bb[j], acc[i][j]);
        }
        __syncthreads();
    }
    float* Gout = g_G + (size_t)b*NS*NS;
    #pragma unroll
    for (int i=0;i<8;i++){
        float* cptr = Gout + (size_t)(m0 + tr*8 + i)*NS + n0 + tc*8;
        *(float4*)(cptr)   = make_float4(acc[i][0],acc[i][1],acc[i][2],acc[i][3]);
        *(float4*)(cptr+4) = make_float4(acc[i][4],acc[i][5],acc[i][6],acc[i][7]);
    }
}

// ---------------------------------------------------------------------------
// Kernel 4: base GEMM for chunk c (c>=1):
//   BASE[b][r][tt] = sum_{s<64c} WQ[b][s][r] * G[b][s][64c+tt]
// 64x64 tile, block 256 (16x16, 4x4/thread), grid (8 row-tiles, 64 b)
// ---------------------------------------------------------------------------
__global__ __launch_bounds__(256) void basegemm_kernel(int c)
{
    __shared__ float As[32][64+1];
    __shared__ float Bs[32][64+1];
    const int tid = threadIdx.x;
    const int r0 = blockIdx.x * 64;
    const int b  = blockIdx.y;
    const int ty = tid >> 4, tx = tid & 15;
    const int tcol0 = c*CS;
    float acc[4][4];
    #pragma unroll
    for (int i=0;i<4;i++)
        #pragma unroll
        for (int j=0;j<4;j++) acc[i][j]=0.f;
    const int K = c*CS;
    for (int k0=0; k0<K; k0+=32){
        #pragma unroll
        for (int i=0;i<8;i++){
            int idx = tid + i*256;
            int kk = idx >> 6, col = idx & 63;
            As[kk][col] = g_WQ[((size_t)b*NS + k0+kk)*NHH + r0 + col];
            Bs[kk][col] = g_G [((size_t)b*NS + k0+kk)*NS  + tcol0 + col];
        }
        __syncthreads();
        #pragma unroll
        for (int kk=0;kk<32;kk++){
            float a[4], bb[4];
            #pragma unroll
            for (int i=0;i<4;i++) a[i]  = As[kk][ty*4+i];
            #pragma unroll
            for (int j=0;j<4;j++) bb[j] = Bs[kk][tx*4+j];
            #pragma unroll
            for (int i=0;i<4;i++)
                #pragma unroll
                for (int j=0;j<4;j++)
                    acc[i][j] = fmaf(a[i], bb[j], acc[i][j]);
        }
        __syncthreads();
    }
    #pragma unroll
    for (int i=0;i<4;i++)
        #pragma unroll
        for (int j=0;j<4;j++)
            g_BASE[((size_t)b*NHH + r0 + ty*4 + i)*CS + tx*4 + j] = acc[i][j];
}

// ---------------------------------------------------------------------------
// Kernel 5: chunk scan. Thread = one (b,row). Pure scalar chain + in-chunk
// triangular accumulation against a 16KB smem G-block. grid (2, 64), 256 thd.
// ---------------------------------------------------------------------------
__global__ __launch_bounds__(256) void scan_kernel(int c, float* __restrict__ vals_out)
{
    __shared__ float Gs[CS][CS+1];
    const int tid = threadIdx.x;
    const int rh  = blockIdx.x;
    const int b   = blockIdx.y;
    const int r   = rh*256 + tid;

    // load in-chunk Gram block (coalesced)
    for (int idx = tid; idx < CS*CS; idx += 256){
        int j = idx >> 6, j2 = idx & 63;
        Gs[j][j2] = g_G[((size_t)b*NS + c*CS + j)*NS + c*CS + j2];
    }
    __syncthreads();

    float vs, vt, P, Q;
    if (c == 0){ vs=0.f; vt=0.f; P=1.f; Q=LRC*OMD; }
    else { vs=g_SVS[b*NHH+r]; vt=g_SVT[b*NHH+r]; P=g_SP[b*NHH+r]; Q=g_SQ[b*NHH+r]; }

    float acc[CS];
    #pragma unroll
    for (int j=0;j<CS;j++) acc[j]=0.f;

    const float* ivp = g_C + ((size_t)(b*NS + c*CS))*N2H + NHH + r;
    const float* bp  = g_BASE + ((size_t)b*NHH + r)*CS;
    float* vp  = vals_out + ((size_t)(b*NS + c*CS))*NHH + r;
    float* wqp = g_WQ     + ((size_t)(b*NS + c*CS))*NHH + r;

    #pragma unroll
    for (int j=0;j<CS;j++){
        float base = 0.f;
        if (c > 0) base = __ldg(bp + j);
        float iv = __ldg(ivp + (size_t)j*N2H);
        float dotraw = acc[j] + base;
        float dtrue = P * dotraw;
        vs = fmaf(vs, ALPHA, fmaf(0.2f, dtrue, iv));
        float v = tanh_approx(vs);
        vp[(size_t)j*NHH] = v;
        vt = fmaf(OMD, v, DECAY*vt);
        float e = LRC*vt*vt;
        P *= (1.0f - e);
        Q *= fmaf(e, fmaf(e, 1.0f + e, 1.0f), 1.0f);   // *= ~1/(1-e)
        float wq = Q*vt;
        wqp[(size_t)j*NHH] = wq;
        #pragma unroll
        for (int j2=j+1;j2<CS;j2++)
            acc[j2] = fmaf(wq, Gs[j][j2], acc[j2]);
    }

    g_SVS[b*NHH+r]=vs; g_SVT[b*NHH+r]=vt; g_SP[b*NHH+r]=P; g_SQ[b*NHH+r]=Q;
}

// ---------------------------------------------------------------------------
// Kernel 6: final mem GEMM: mem[b][r][j] = P[r] * sum_s WQ[b][s][r]*KTP[b][s][j]
// M=N=512, K=256, 128x128 tiles, grid (4,4,64)
// ---------------------------------------------------------------------------
__global__ __launch_bounds__(256) void memgemm_kernel(float* __restrict__ mem_out)
{
    __shared__ float As[32][128+4];
    __shared__ float Bs[32][128+4];
    const int tid = threadIdx.x;
    const int b  = blockIdx.z;
    const int r0 = blockIdx.y * 128;
    const int j0 = blockIdx.x * 128;
    const int tr = tid >> 4, tc = tid & 15;
    float acc[8][8];
    #pragma unroll
    for (int i=0;i<8;i++)
        #pragma unroll
        for (int j=0;j<8;j++) acc[i][j]=0.f;
    for (int k0=0; k0<NS; k0+=32){
        #pragma unroll
        for (int i=0;i<16;i++){
            int idx = tid + i*256;
            int kk = idx >> 7, col = idx & 127;
            As[kk][col] = g_WQ [((size_t)b*NS + k0+kk)*NHH + r0 + col];
            Bs[kk][col] = g_KTP[((size_t)b*NS + k0+kk)*NHH + j0 + col];
        }
        __syncthreads();
        #pragma unroll
        for (int kk=0;kk<32;kk++){
            float a[8], bb[8];
            *(float4*)(a)    = *(const float4*)(&As[kk][tr*8]);
            *(float4*)(a+4)  = *(const float4*)(&As[kk][tr*8+4]);
            *(float4*)(bb)   = *(const float4*)(&Bs[kk][tc*8]);
            *(float4*)(bb+4) = *(const float4*)(&Bs[kk][tc*8+4]);
            #pragma unroll
            for (int i=0;i<8;i++)
                #pragma unroll
                for (int j=0;j<8;j++)
                    acc[i][j] = fmaf(a[i], bb[j], acc[i][j]);
        }
        __syncthreads();
    }
    #pragma unroll
    for (int i=0;i<8;i++){
        float p = g_SP[b*NHH + r0 + tr*8 + i];
        float* cptr = mem_out + ((size_t)b*NHH + r0 + tr*8 + i)*NHH + j0 + tc*8;
        *(float4*)(cptr)   = make_float4(acc[i][0]*p,acc[i][1]*p,acc[i][2]*p,acc[i][3]*p);
        *(float4*)(cptr+4) = make_float4(acc[i][4]*p,acc[i][5]*p,acc[i][6]*p,acc[i][7]*p);
    }
}

// ---------------------------------------------------------------------------
extern "C" void kernel_launch(void* const* d_in, const int* in_sizes, int n_in,
                              void* d_out, int out_size)
{
    const float* x = (const float*)d_in[0];   // [64,256,256]
    const float* W = (const float*)d_in[1];   // [1024,256]
    float* out = (float*)d_out;
    float* mem_out  = out;                                    // [64,512,512]
    float* keys_out = out + (size_t)NB*NHH*NHH;               // [64,256,512]
    float* vals_out = keys_out + (size_t)NB*NS*NHH;           // [64,256,512]

    sgemm_kernel<<<dim3(N2H/128, NM/128), 256>>>(x, W);       // (8,128)
    tracek_kernel<<<(NB*NHH)/256, 256>>>(keys_out);
    gram_kernel<<<dim3(2, 2, NB), 256>>>(keys_out);
    for (int c = 0; c < NC; c++){
        if (c > 0) basegemm_kernel<<<dim3(NHH/64, NB), 256>>>(c);
        scan_kernel<<<dim3(2, NB), 256>>>(c, vals_out);
    }
    memgemm_kernel<<<dim3(4, 4, NB), 256>>>(mem_out);
}

// round 13
// speedup vs baseline: 1.5814x; 1.0917x over previous
#include <cuda_runtime.h>
#include <cuda_bf16.h>
#include <cstdint>

#define NB 64
#define NS 256
#define NI 256
#define NHH 512
#define N2H 1024
#define NM (NB*NS)
#define CS 64          // scan chunk size
#define NC (NS/CS)     // 4 chunks

// Scratch (static device arrays)
static __device__ float g_C  [(size_t)NM * N2H];        // x@W^T           64MB
static __device__ float g_KTP[(size_t)NB * NS * NHH];   // kt' traces      33MB
static __device__ float g_WQ [(size_t)NB * NS * NHH];   // wq[b][s][r]     33MB
static __device__ float g_G  [(size_t)NB * NS * NS];    // Gram[b][s][t]   16MB
static __device__ float g_BASE[(size_t)NB * NHH * CS];  // per-chunk base   8MB
static __device__ float g_SVS[NB*NHH], g_SVT[NB*NHH], g_SP[NB*NHH], g_SQ[NB*NHH];

__device__ __forceinline__ float fast_tanh(float x){
    float z = __expf(2.0f * x);
    return 1.0f - __fdividef(2.0f, z + 1.0f);
}
__device__ __forceinline__ float tanh_approx(float x){
    float r; asm("tanh.approx.f32 %0, %1;" : "=f"(r) : "f"(x)); return r;
}

#define ALPHA 0.9048374180359595f
#define DECAY 0.9512294245007140f
#define OMD   0.0487705754992860f
#define LRC   0.01f

// ---------------------------------------------------------------------------
// Kernel 1: SGEMM  C[m][n] = sum_k x[m][k]*W[n][k]  (measured 201us)
// ---------------------------------------------------------------------------
__global__ __launch_bounds__(256) void sgemm_kernel(const float* __restrict__ A,
                                                    const float* __restrict__ W)
{
    __shared__ float As[32][128+4];
    __shared__ float Bs[32][128+4];
    const int tid = threadIdx.x;
    const int m0 = blockIdx.y * 128;
    const int n0 = blockIdx.x * 128;
    const int tr = tid >> 4, tc = tid & 15;
    float acc[8][8];
    #pragma unroll
    for (int i=0;i<8;i++)
        #pragma unroll
        for (int j=0;j<8;j++) acc[i][j]=0.f;
    const int lr = tid >> 3, lc = (tid & 7) << 2;
    for (int k0=0; k0<NI; k0+=32){
        #pragma unroll
        for (int h=0; h<4; h++){
            int r = lr + h*32;
            float4 av = *(const float4*)(A + (size_t)(m0+r)*NI + k0 + lc);
            As[lc+0][r]=av.x; As[lc+1][r]=av.y; As[lc+2][r]=av.z; As[lc+3][r]=av.w;
            float4 bv = *(const float4*)(W + (size_t)(n0+r)*NI + k0 + lc);
            Bs[lc+0][r]=bv.x; Bs[lc+1][r]=bv.y; Bs[lc+2][r]=bv.z; Bs[lc+3][r]=bv.w;
        }
        __syncthreads();
        #pragma unroll
        for (int kk=0;kk<32;kk++){
            float a[8], bb[8];
            *(float4*)(a)    = *(const float4*)(&As[kk][tr*8]);
            *(float4*)(a+4)  = *(const float4*)(&As[kk][tr*8+4]);
            *(float4*)(bb)   = *(const float4*)(&Bs[kk][tc*8]);
            *(float4*)(bb+4) = *(const float4*)(&Bs[kk][tc*8+4]);
            #pragma unroll
            for (int i=0;i<8;i++)
                #pragma unroll
                for (int j=0;j<8;j++)
                    acc[i][j] = fmaf(a[i], bb[j], acc[i][j]);
        }
        __syncthreads();
    }
    #pragma unroll
    for (int i=0;i<8;i++){
        float* cptr = g_C + (size_t)(m0 + tr*8 + i)*N2H + n0 + tc*8;
        *(float4*)(cptr)   = make_float4(acc[i][0],acc[i][1],acc[i][2],acc[i][3]);
        *(float4*)(cptr+4) = make_float4(acc[i][4],acc[i][5],acc[i][6],acc[i][7]);
    }
}

// ---------------------------------------------------------------------------
// Kernel 2: per-(b,h) sequential traces: keys = tanh(ks), kt' = d*kt' + key
// ---------------------------------------------------------------------------
__global__ __launch_bounds__(256) void tracek_kernel(float* __restrict__ keys_out)
{
    int gid = blockIdx.x*blockDim.x + threadIdx.x;
    int b = gid >> 9, h = gid & 511;
    const float* c = g_C + (size_t)b*NS*N2H + h;
    float* ko = keys_out + (size_t)b*NS*NHH + h;
    float* kp = g_KTP    + (size_t)b*NS*NHH + h;
    float ks = 0.f, kt = 0.f;
    #pragma unroll 8
    for (int t=0;t<NS;t++){
        ks = fmaf(ks, ALPHA, __ldg(c + (size_t)t*N2H));
        float k = fast_tanh(ks);
        ko[(size_t)t*NHH] = k;
        kt = fmaf(kt, DECAY, k);
        kp[(size_t)t*NHH] = kt;
    }
}

// ---------------------------------------------------------------------------
// Kernel 3: batched Gram  G[b][s][t] = sum_h KTP[b][s][h]*keys[b][t][h]
// Lower-left 128x128 block (s>t) never read -> 3 tiles, grid (3, 64).
// ---------------------------------------------------------------------------
__global__ __launch_bounds__(256) void gram_kernel(const float* __restrict__ keys)
{
    __shared__ float As[32][128+4];
    __shared__ float Bs[32][128+4];
    const int tid = threadIdx.x;
    const int b  = blockIdx.y;
    const int bi = blockIdx.x;           // 0,1,2 -> (bx,by) in {(0,0),(1,0),(1,1)}
    const int bx = (bi >= 1) ? 1 : 0;
    const int by = (bi == 2) ? 1 : 0;
    const int m0 = by * 128;
    const int n0 = bx * 128;
    const float* A = g_KTP + (size_t)b*NS*NHH;
    const float* B = keys  + (size_t)b*NS*NHH;
    const int tr = tid >> 4, tc = tid & 15;
    float acc[8][8];
    #pragma unroll
    for (int i=0;i<8;i++)
        #pragma unroll
        for (int j=0;j<8;j++) acc[i][j]=0.f;
    const int lr = tid >> 3, lc = (tid & 7) << 2;
    for (int k0=0; k0<NHH; k0+=32){
        #pragma unroll
        for (int h=0; h<4; h++){
            int r = lr + h*32;
            float4 av = *(const float4*)(A + (size_t)(m0+r)*NHH + k0 + lc);
            As[lc+0][r]=av.x; As[lc+1][r]=av.y; As[lc+2][r]=av.z; As[lc+3][r]=av.w;
            float4 bv = *(const float4*)(B + (size_t)(n0+r)*NHH + k0 + lc);
            Bs[lc+0][r]=bv.x; Bs[lc+1][r]=bv.y; Bs[lc+2][r]=bv.z; Bs[lc+3][r]=bv.w;
        }
        __syncthreads();
        #pragma unroll
        for (int kk=0;kk<32;kk++){
            float a[8], bb[8];
            *(float4*)(a)    = *(const float4*)(&As[kk][tr*8]);
            *(float4*)(a+4)  = *(const float4*)(&As[kk][tr*8+4]);
            *(float4*)(bb)   = *(const float4*)(&Bs[kk][tc*8]);
            *(float4*)(bb+4) = *(const float4*)(&Bs[kk][tc*8+4]);
            #pragma unroll
            for (int i=0;i<8;i++)
                #pragma unroll
                for (int j=0;j<8;j++)
                    acc[i][j] = fmaf(a[i], bb[j], acc[i][j]);
        }
        __syncthreads();
    }
    float* Gout = g_G + (size_t)b*NS*NS;
    #pragma unroll
    for (int i=0;i<8;i++){
        float* cptr = Gout + (size_t)(m0 + tr*8 + i)*NS + n0 + tc*8;
        *(float4*)(cptr)   = make_float4(acc[i][0],acc[i][1],acc[i][2],acc[i][3]);
        *(float4*)(cptr+4) = make_float4(acc[i][4],acc[i][5],acc[i][6],acc[i][7]);
    }
}

// ---------------------------------------------------------------------------
// Kernel 4: base GEMM for chunk c (c>=1)
// ---------------------------------------------------------------------------
__global__ __launch_bounds__(256) void basegemm_kernel(int c)
{
    __shared__ float As[32][64+1];
    __shared__ float Bs[32][64+1];
    const int tid = threadIdx.x;
    const int r0 = blockIdx.x * 64;
    const int b  = blockIdx.y;
    const int ty = tid >> 4, tx = tid & 15;
    const int tcol0 = c*CS;
    float acc[4][4];
    #pragma unroll
    for (int i=0;i<4;i++)
        #pragma unroll
        for (int j=0;j<4;j++) acc[i][j]=0.f;
    const int K = c*CS;
    for (int k0=0; k0<K; k0+=32){
        #pragma unroll
        for (int i=0;i<8;i++){
            int idx = tid + i*256;
            int kk = idx >> 6, col = idx & 63;
            As[kk][col] = g_WQ[((size_t)b*NS + k0+kk)*NHH + r0 + col];
            Bs[kk][col] = g_G [((size_t)b*NS + k0+kk)*NS  + tcol0 + col];
        }
        __syncthreads();
        #pragma unroll
        for (int kk=0;kk<32;kk++){
            float a[4], bb[4];
            #pragma unroll
            for (int i=0;i<4;i++) a[i]  = As[kk][ty*4+i];
            #pragma unroll
            for (int j=0;j<4;j++) bb[j] = Bs[kk][tx*4+j];
            #pragma unroll
            for (int i=0;i<4;i++)
                #pragma unroll
                for (int j=0;j<4;j++)
                    acc[i][j] = fmaf(a[i], bb[j], acc[i][j]);
        }
        __syncthreads();
    }
    #pragma unroll
    for (int i=0;i<4;i++)
        #pragma unroll
        for (int j=0;j<4;j++)
            g_BASE[((size_t)b*NHH + r0 + ty*4 + i)*CS + tx*4 + j] = acc[i][j];
}

// ---------------------------------------------------------------------------
// Kernel 5: chunk scan (unchanged)
// ---------------------------------------------------------------------------
__global__ __launch_bounds__(256) void scan_kernel(int c, float* __restrict__ vals_out)
{
    __shared__ float Gs[CS][CS+1];
    const int tid = threadIdx.x;
    const int rh  = blockIdx.x;
    const int b   = blockIdx.y;
    const int r   = rh*256 + tid;

    for (int idx = tid; idx < CS*CS; idx += 256){
        int j = idx >> 6, j2 = idx & 63;
        Gs[j][j2] = g_G[((size_t)b*NS + c*CS + j)*NS + c*CS + j2];
    }
    __syncthreads();

    float vs, vt, P, Q;
    if (c == 0){ vs=0.f; vt=0.f; P=1.f; Q=LRC*OMD; }
    else { vs=g_SVS[b*NHH+r]; vt=g_SVT[b*NHH+r]; P=g_SP[b*NHH+r]; Q=g_SQ[b*NHH+r]; }

    float acc[CS];
    #pragma unroll
    for (int j=0;j<CS;j++) acc[j]=0.f;

    const float* ivp = g_C + ((size_t)(b*NS + c*CS))*N2H + NHH + r;
    const float* bp  = g_BASE + ((size_t)b*NHH + r)*CS;
    float* vp  = vals_out + ((size_t)(b*NS + c*CS))*NHH + r;
    float* wqp = g_WQ     + ((size_t)(b*NS + c*CS))*NHH + r;

    #pragma unroll
    for (int j=0;j<CS;j++){
        float base = 0.f;
        if (c > 0) base = __ldg(bp + j);
        float iv = __ldg(ivp + (size_t)j*N2H);
        float dotraw = acc[j] + base;
        float dtrue = P * dotraw;
        vs = fmaf(vs, ALPHA, fmaf(0.2f, dtrue, iv));
        float v = tanh_approx(vs);
        vp[(size_t)j*NHH] = v;
        vt = fmaf(OMD, v, DECAY*vt);
        float e = LRC*vt*vt;
        P *= (1.0f - e);
        Q *= fmaf(e, fmaf(e, 1.0f + e, 1.0f), 1.0f);
        float wq = Q*vt;
        wqp[(size_t)j*NHH] = wq;
        #pragma unroll
        for (int j2=j+1;j2<CS;j2++)
            acc[j2] = fmaf(wq, Gs[j][j2], acc[j2]);
    }

    g_SVS[b*NHH+r]=vs; g_SVT[b*NHH+r]=vt; g_SP[b*NHH+r]=P; g_SQ[b*NHH+r]=Q;
}

// ---------------------------------------------------------------------------
// Kernel 6: final mem GEMM on HMMA (mma.sync bf16, hi/lo split, 3 passes):
//   mem[b][r][j] = P[r] * sum_s WQ[b][s][r]*KTP[b][s][j]
// CTA tile 128(M) x 128(N), 8 warps (2x4), warp tile 64x32, K-loop 8x32.
// smem: A[m][k], B[n][k] bf16 hi/lo, stride 40 (conflict-free frag loads).
// Fragments loaded per documented m16n8k16 mapping (g=lane>>2, t=lane&3).
// ---------------------------------------------------------------------------
#define MG_LD 40

__device__ __forceinline__ void mma_bf16(float c[4], uint32_t a0, uint32_t a1,
                                         uint32_t a2, uint32_t a3,
                                         uint32_t b0, uint32_t b1){
    asm volatile(
        "mma.sync.aligned.m16n8k16.row.col.f32.bf16.bf16.f32 "
        "{%0,%1,%2,%3}, {%4,%5,%6,%7}, {%8,%9}, {%0,%1,%2,%3};"
        : "+f"(c[0]), "+f"(c[1]), "+f"(c[2]), "+f"(c[3])
        : "r"(a0), "r"(a1), "r"(a2), "r"(a3), "r"(b0), "r"(b1));
}

__global__ __launch_bounds__(256) void memgemm_mma(float* __restrict__ mem_out)
{
    __shared__ unsigned short Ah[128*MG_LD], Al[128*MG_LD];
    __shared__ unsigned short Bh[128*MG_LD], Bl[128*MG_LD];

    const int tid = threadIdx.x;
    const int wid = tid >> 5, lane = tid & 31;
    const int g = lane >> 2, t = lane & 3;
    const int n0 = blockIdx.x * 128;
    const int r0 = blockIdx.y * 128;
    const int b  = blockIdx.z;
    const int wm = (wid >> 2) * 64;   // warp m offset: 0 or 64
    const int wn = (wid & 3) * 32;    // warp n offset: 0,32,64,96

    float c[4][4][4];                 // [mt][nt][4]
    #pragma unroll
    for (int i=0;i<4;i++)
        #pragma unroll
        for (int j=0;j<4;j++)
            #pragma unroll
            for (int q=0;q<4;q++) c[i][j][q]=0.f;

    for (int k0 = 0; k0 < NS; k0 += 32){
        // stage: 4096 elems each of A (WQ^T tile) and B (KTP^T tile), hi/lo
        #pragma unroll
        for (int i = 0; i < 16; i++){
            int idx = tid + i*256;
            int m = idx & 127, k = idx >> 7;
            float va = __ldg(g_WQ  + ((size_t)b*NS + k0 + k)*NHH + r0 + m);
            float vb = __ldg(g_KTP + ((size_t)b*NS + k0 + k)*NHH + n0 + m);
            __nv_bfloat16 ha = __float2bfloat16(va);
            __nv_bfloat16 hb = __float2bfloat16(vb);
            __nv_bfloat16 la = __float2bfloat16(va - __bfloat162float(ha));
            __nv_bfloat16 lb = __float2bfloat16(vb - __bfloat162float(hb));
            Ah[m*MG_LD + k] = __bfloat16_as_ushort(ha);
            Al[m*MG_LD + k] = __bfloat16_as_ushort(la);
            Bh[m*MG_LD + k] = __bfloat16_as_ushort(hb);
            Bl[m*MG_LD + k] = __bfloat16_as_ushort(lb);
        }
        __syncthreads();

        #pragma unroll
        for (int ks = 0; ks < 32; ks += 16){
            // A fragments (hi & lo) for 4 m-tiles
            uint32_t ah[4][4], al[4][4];
            #pragma unroll
            for (int mt=0; mt<4; mt++){
                int row = wm + mt*16;
                int o00 = (row + g    )*MG_LD + ks + 2*t;
                int o10 = (row + g + 8)*MG_LD + ks + 2*t;
                ah[mt][0] = *(const uint32_t*)&Ah[o00];
                ah[mt][1] = *(const uint32_t*)&Ah[o10];
                ah[mt][2] = *(const uint32_t*)&Ah[o00 + 8];
                ah[mt][3] = *(const uint32_t*)&Ah[o10 + 8];
                al[mt][0] = *(const uint32_t*)&Al[o00];
                al[mt][1] = *(const uint32_t*)&Al[o10];
                al[mt][2] = *(const uint32_t*)&Al[o00 + 8];
                al[mt][3] = *(const uint32_t*)&Al[o10 + 8];
            }
            // B fragments for 4 n-tiles
            uint32_t bh[4][2], bl[4][2];
            #pragma unroll
            for (int nt=0; nt<4; nt++){
                int n = wn + nt*8 + g;
                int o = n*MG_LD + ks + 2*t;
                bh[nt][0] = *(const uint32_t*)&Bh[o];
                bh[nt][1] = *(const uint32_t*)&Bh[o + 8];
                bl[nt][0] = *(const uint32_t*)&Bl[o];
                bl[nt][1] = *(const uint32_t*)&Bl[o + 8];
            }
            #pragma unroll
            for (int mt=0; mt<4; mt++)
                #pragma unroll
                for (int nt=0; nt<4; nt++){
                    mma_bf16(c[mt][nt], ah[mt][0],ah[mt][1],ah[mt][2],ah[mt][3], bh[nt][0],bh[nt][1]);
                    mma_bf16(c[mt][nt], ah[mt][0],ah[mt][1],ah[mt][2],ah[mt][3], bl[nt][0],bl[nt][1]);
                    mma_bf16(c[mt][nt], al[mt][0],al[mt][1],al[mt][2],al[mt][3], bh[nt][0],bh[nt][1]);
                }
        }
        __syncthreads();
    }

    // epilogue: scale by P[row] and store (c0,c1 -> row g; c2,c3 -> row g+8)
    #pragma unroll
    for (int mt=0; mt<4; mt++){
        int row0g = r0 + wm + mt*16 + g;
        float p0 = g_SP[b*NHH + row0g];
        float p1 = g_SP[b*NHH + row0g + 8];
        #pragma unroll
        for (int nt=0; nt<4; nt++){
            int n = n0 + wn + nt*8 + 2*t;
            float* o0 = mem_out + ((size_t)b*NHH + row0g)*NHH + n;
            float* o1 = o0 + 8*NHH;
            o0[0] = c[mt][nt][0]*p0;  o0[1] = c[mt][nt][1]*p0;
            o1[0] = c[mt][nt][2]*p1;  o1[1] = c[mt][nt][3]*p1;
        }
    }
}

// ---------------------------------------------------------------------------
extern "C" void kernel_launch(void* const* d_in, const int* in_sizes, int n_in,
                              void* d_out, int out_size)
{
    const float* x = (const float*)d_in[0];   // [64,256,256]
    const float* W = (const float*)d_in[1];   // [1024,256]
    float* out = (float*)d_out;
    float* mem_out  = out;                                    // [64,512,512]
    float* keys_out = out + (size_t)NB*NHH*NHH;               // [64,256,512]
    float* vals_out = keys_out + (size_t)NB*NS*NHH;           // [64,256,512]

    sgemm_kernel<<<dim3(N2H/128, NM/128), 256>>>(x, W);       // (8,128)
    tracek_kernel<<<(NB*NHH)/256, 256>>>(keys_out);
    gram_kernel<<<dim3(3, NB), 256>>>(keys_out);
    for (int c = 0; c < NC; c++){
        if (c > 0) basegemm_kernel<<<dim3(NHH/64, NB), 256>>>(c);
        scan_kernel<<<dim3(2, NB), 256>>>(c, vals_out);
    }
    memgemm_mma<<<dim3(4, 4, NB), 256>>>(mem_out);
}